// round 2
// baseline (speedup 1.0000x reference)
#include <cuda_runtime.h>
#include <cstdint>

#define CTC_V 128
#define NS 8            // cp.async ring slots (power of 2)
#define NEG2 (-1.0e30f) // log2-domain stand-in for -inf (matches reference NEG)

// Scratch: log2-softmax probabilities (T*B*V) and per-example costs (nats).
__device__ float g_probs[1024 * 64 * 128];
__device__ float g_costs[1024];

// ---------------------------------------------------------------------------
// Kernel 1: log2-softmax over V=128 per (t,b) row. One warp per row, float4 IO.
// lp2 = (x - m)*log2(e) ... computed directly in base-2: lp2 = x*L2E - max2 - log2(sum)
// ---------------------------------------------------------------------------
__global__ void softmax_k(const float* __restrict__ acts, int rows) {
    int gw   = (blockIdx.x * blockDim.x + threadIdx.x) >> 5;
    int lane = threadIdx.x & 31;
    if (gw >= rows) return;
    const float L2E = 1.4426950408889634f;
    const float4* src = reinterpret_cast<const float4*>(acts) + (size_t)gw * 32 + lane;
    float4 v = *src;
    // work in base-2 from the start
    float x0 = v.x * L2E, x1 = v.y * L2E, x2 = v.z * L2E, x3 = v.w * L2E;
    float m = fmaxf(fmaxf(x0, x1), fmaxf(x2, x3));
#pragma unroll
    for (int o = 16; o; o >>= 1) m = fmaxf(m, __shfl_xor_sync(0xffffffffu, m, o));
    float e0 = exp2f(x0 - m), e1 = exp2f(x1 - m);
    float e2 = exp2f(x2 - m), e3 = exp2f(x3 - m);
    float ssum = e0 + e1 + e2 + e3;
#pragma unroll
    for (int o = 16; o; o >>= 1) ssum += __shfl_xor_sync(0xffffffffu, ssum, o);
    float ls = log2f(ssum);
    float4 o4 = make_float4(x0 - m - ls, x1 - m - ls, x2 - m - ls, x3 - m - ls);
    reinterpret_cast<float4*>(g_probs)[(size_t)gw * 32 + lane] = o4;
}

// ---------------------------------------------------------------------------
// Kernel 2: CTC alpha recursion, log2 domain (exact reference semantics).
// One CTA per batch element, one thread per extended state (S = 2L+1).
// Prob rows streamed via cp.async ring.
// ---------------------------------------------------------------------------
extern __shared__ float smem_dyn[];

__global__ __launch_bounds__(576, 1) void ctc_alpha_k(
    const int* __restrict__ labels, const int* __restrict__ act_lens,
    const int* __restrict__ label_lens, int T, int B, int L)
{
    const int V = CTC_V;
    int b   = blockIdx.x;
    int S   = 2 * L + 1;
    int BD  = blockDim.x;
    float* rowbuf = smem_dyn;                 // NS * V
    float* aA     = rowbuf + NS * V;          // BD + 2
    float* aB     = aA + BD + 2;              // BD + 2

    int tid  = threadIdx.x;
    int lane = tid & 31;
    int Tlen = act_lens[b];
    if (Tlen > T) Tlen = T;
    if (Tlen < 1) Tlen = 1;
    int Lb = label_lens[b];

    // Per-thread extended-label value and skip-transition mask.
    int  s      = tid;
    int  extv   = 0;
    bool allow  = false;
    bool active = (s < S);
    if ((s & 1) && s < S) {
        extv = labels[b * L + (s >> 1)];
        if (s >= 3) {
            int pv = labels[b * L + ((s - 2) >> 1)];
            allow = (extv != pv);
        }
    }
    if (tid < 2) { aA[tid] = NEG2; aB[tid] = NEG2; }  // left padding = -inf

    const float* prow0   = g_probs + (size_t)b * V;
    size_t       rstride = (size_t)B * V;

    // cp.async prologue: fill slots 0..NS-2.
    if (tid < 32) {
#pragma unroll
        for (int i = 0; i < NS - 1; ++i) {
            if (i < Tlen) {
                uint32_t dst = (uint32_t)__cvta_generic_to_shared(rowbuf + i * V) + lane * 16;
                const float* src = prow0 + (size_t)i * rstride + lane * 4;
                asm volatile("cp.async.cg.shared.global [%0], [%1], 16;" :: "r"(dst), "l"(src));
            }
            asm volatile("cp.async.commit_group;");
        }
        asm volatile("cp.async.wait_group 5;");
    }
    __syncthreads();

    // t = 0 init: alpha0[0] = lp2(blank), alpha0[1] = lp2(label0), else -inf.
    float c = NEG2;
    if (s == 0)      c = rowbuf[0];
    else if (s == 1) c = rowbuf[extv];
    aA[tid + 2] = c;

    float* cur = aA;
    float* nxt = aB;

    for (int t = 1; t < Tlen; ++t) {
        if (tid < 32) asm volatile("cp.async.wait_group 5;");
        __syncthreads();   // orders prev-step alpha writes/reads AND row availability

        // Prefetch row t+NS-2 into slot (t+NS-2)%NS (that slot was last read at t-2).
        int tp = t + NS - 2;
        if (tid < 32) {
            if (tp < Tlen) {
                uint32_t dst = (uint32_t)__cvta_generic_to_shared(rowbuf + (tp & (NS - 1)) * V)
                               + lane * 16;
                const float* src = prow0 + (size_t)tp * rstride + lane * 4;
                asm volatile("cp.async.cg.shared.global [%0], [%1], 16;" :: "r"(dst), "l"(src));
            }
            asm volatile("cp.async.commit_group;");
        }

        const float* row = rowbuf + (t & (NS - 1)) * V;

        float emit = row[extv];
        float p1   = cur[tid + 1];                  // alpha[s-1]
        float p2   = allow ? cur[tid] : NEG2;       // alpha[s-2] (masked)
        float m  = fmaxf(fmaxf(c, p1), p2);
        float r  = exp2f(c - m) + exp2f(p1 - m) + exp2f(p2 - m);
        float nv = m + log2f(r) + emit;
        nv = active ? nv : NEG2;
        nxt[tid + 2] = nv;
        c = nv;

        float* tmp = cur; cur = nxt; nxt = tmp;
    }
    __syncthreads();

    if (tid == 0) {
        int end = 2 * Lb;
        if (end > S - 1) end = S - 1;
        float a0 = cur[end + 2];       // alpha[end]
        float a1 = cur[end + 1];       // alpha[end-1] (padding gives -inf if end==0)
        float m  = fmaxf(a0, a1);
        float l2sum = m + log2f(exp2f(a0 - m) + exp2f(a1 - m));
        g_costs[b] = -l2sum * 0.69314718055994530942f;   // convert log2 -> nats
    }
}

// ---------------------------------------------------------------------------
// Kernel 3: deterministic sum of per-example costs.
// ---------------------------------------------------------------------------
__global__ void reduce_k(float* out, int B) {
    float sum = 0.0f;
    for (int i = threadIdx.x; i < B; i += 32) sum += g_costs[i];
#pragma unroll
    for (int o = 16; o; o >>= 1) sum += __shfl_xor_sync(0xffffffffu, sum, o);
    if (threadIdx.x == 0) *out = sum;
}

// ---------------------------------------------------------------------------
extern "C" void kernel_launch(void* const* d_in, const int* in_sizes, int n_in,
                              void* d_out, int out_size)
{
    const float* acts      = (const float*)d_in[0];
    const int*   labels    = (const int*)d_in[1];
    const int*   act_lens  = (const int*)d_in[2];
    const int*   label_len = (const int*)d_in[3];

    int B = in_sizes[2];
    int L = in_sizes[1] / B;
    int V = CTC_V;
    int T = in_sizes[0] / (B * V);

    int rows = T * B;
    softmax_k<<<(rows + 7) / 8, 256>>>(acts, rows);

    int S  = 2 * L + 1;
    int BD = ((S + 31) / 32) * 32;
    size_t smem = (size_t)(NS * V + 2 * (BD + 2)) * sizeof(float);
    ctc_alpha_k<<<B, BD, smem>>>(labels, act_lens, label_len, T, B, L);

    reduce_k<<<1, 32>>>((float*)d_out, B);
}